// round 14
// baseline (speedup 1.0000x reference)
#include <cuda_runtime.h>
#include <cuda_bf16.h>
#include <cuda_fp16.h>
#include <mma.h>
#include <cstdint>

using namespace nvcuda;

// Problem constants (fixed by the dataset)
#define NN 50000
#define EE 800000
#define TOT_E (EE + NN)   // edges + self loops = 850000

// ---------------- scratch (no allocations allowed) ----------------
__device__ __align__(16) float g_C1[NN * 256];   // [xl1 | xr1] per node (128+128)
__device__ __align__(16) float g_h [NN * 128];   // layer-1 output after ELU
__device__ __align__(16) float g_C2[NN * 128];   // [xl2 | xr2] per node (64+64)
__device__ __align__(16) __half g_x1h[NN * 128];  // fp16 compact xl1 (gather operand)
__device__ __align__(16) __half g_x2h[NN * 64];   // fp16 compact xl2
__device__ __align__(16) __nv_bfloat16 g_Ah[NN * 128];   // A hi (bf16 split)
__device__ __align__(16) __nv_bfloat16 g_Al[NN * 128];   // A lo
__device__ __align__(16) __nv_bfloat16 g_Bh[256 * 128];  // layer-1 W transposed [n][k] hi
__device__ __align__(16) __nv_bfloat16 g_Bl[256 * 128];  // layer-1 W transposed [n][k] lo
__device__ __align__(16) __nv_bfloat16 g_Bh2[128 * 128]; // layer-2 W transposed hi
__device__ __align__(16) __nv_bfloat16 g_Bl2[128 * 128]; // layer-2 W transposed lo
__device__ int   g_deg[NN];
__device__ int   g_tmp[NN];
__device__ int   g_off[NN + 1];
__device__ int   g_cur[NN];
__device__ int   g_bsum[64];
__device__ int   g_csr[TOT_E];
__device__ int   g_is64;          // 1 if edge_index is int64, 0 if int32

// ---------------- edge-index dtype handling ----------------
__device__ __forceinline__ int edge_at(const void* ei, int idx) {
    if (g_is64) return (int)((const long long*)ei)[idx];
    return ((const int*)ei)[idx];
}

// ---------------- CSR build (compressed: detect folded into init) ----------------
__global__ void k_init(const void* __restrict__ ei) {
    int i = blockIdx.x * blockDim.x + threadIdx.x;
    if (i < NN) g_deg[i] = 1;   // self loop
    if (i == 0) {
        const long long* p = (const long long*)ei;
        int ok = 1;
        for (int j = 0; j < 64; j++) {
            long long v = p[j];
            if (v < 0 || v >= NN) { ok = 0; break; }
        }
        g_is64 = ok;
    }
}

__global__ void k_hist(const void* __restrict__ ei) {
    int e = blockIdx.x * blockDim.x + threadIdx.x;
    if (e < EE) {
        int d = edge_at(ei, EE + e);
        atomicAdd(&g_deg[d], 1);
    }
}

__global__ void k_scan1() {
    __shared__ int sh[1024];
    int t = threadIdx.x;
    int i = blockIdx.x * 1024 + t;
    int v = (i < NN) ? g_deg[i] : 0;
    sh[t] = v;
    __syncthreads();
    #pragma unroll
    for (int off = 1; off < 1024; off <<= 1) {
        int x = (t >= off) ? sh[t - off] : 0;
        __syncthreads();
        sh[t] += x;
        __syncthreads();
    }
    if (i < NN) g_tmp[i] = sh[t] - v;
    if (t == 1023) g_bsum[blockIdx.x] = sh[1023];
}

// scan3 with scan2 folded in (block leader sums prior block totals)
__global__ void k_scan3() {
    __shared__ int base;
    if (threadIdx.x == 0) {
        int run = 0;
        for (int b = 0; b < (int)blockIdx.x; b++) run += g_bsum[b];
        base = run;
    }
    __syncthreads();
    int i = blockIdx.x * 1024 + threadIdx.x;
    if (i < NN) {
        int off = g_tmp[i] + base;
        g_off[i] = off;
        g_cur[i] = off;
        if (i == NN - 1) g_off[NN] = off + g_deg[i];
    }
}

__global__ void k_scatter(const void* __restrict__ ei) {
    int id = blockIdx.x * blockDim.x + threadIdx.x;
    if (id >= TOT_E) return;
    int s, d;
    if (id < EE) { s = edge_at(ei, id); d = edge_at(ei, EE + id); }
    else         { s = d = id - EE; }
    int p = atomicAdd(&g_cur[d], 1);
    g_csr[p] = s;
}

// ---------------- precompute bf16 hi/lo splits ----------------
__device__ __forceinline__ void bf16_split(float v, __nv_bfloat16& h, __nv_bfloat16& l) {
    h = __float2bfloat16(v);
    l = __float2bfloat16(v - __bfloat162float(h));
}

__global__ void k_convA1(const float* __restrict__ A) {
    int i = blockIdx.x * blockDim.x + threadIdx.x;   // one per 4 elements
    if (i >= NN * 32) return;
    float4 v = *(const float4*)&A[i * 4];
    __nv_bfloat16 h[4], l[4];
    bf16_split(v.x, h[0], l[0]);
    bf16_split(v.y, h[1], l[1]);
    bf16_split(v.z, h[2], l[2]);
    bf16_split(v.w, h[3], l[3]);
    *(uint2*)&g_Ah[i * 4] = *(uint2*)h;
    *(uint2*)&g_Al[i * 4] = *(uint2*)l;
}

template <int LAYER>
__global__ void k_convW(const float* __restrict__ B0, const float* __restrict__ B1) {
    const int split = (LAYER == 1) ? 128 : 64;
    const int NB = 2 * split;
    __nv_bfloat16* Dh = (LAYER == 1) ? g_Bh : g_Bh2;
    __nv_bfloat16* Dl = (LAYER == 1) ? g_Bl : g_Bl2;
    int idx = blockIdx.x * blockDim.x + threadIdx.x;
    if (idx >= NB * 128) return;
    int n = idx % NB, k = idx / NB;
    const float* W = (n < split) ? B0 : B1;
    int wc = (n < split) ? n : n - split;
    float v = W[k * split + wc];
    __nv_bfloat16 h, l;
    bf16_split(v, h, l);
    Dh[n * 128 + k] = h;
    Dl[n * 128 + k] = l;
}

// ---------------- pack xl halves into compact fp16 ----------------
__global__ void k_pack1() {
    int i = blockIdx.x * blockDim.x + threadIdx.x;   // one per 4 elems, N*32 total
    if (i >= NN * 32) return;
    int r = i >> 5, q = i & 31;
    float4 v = *(const float4*)&g_C1[r * 256 + q * 4];
    __half h[4] = { __float2half(v.x), __float2half(v.y), __float2half(v.z), __float2half(v.w) };
    *(uint2*)&g_x1h[r * 128 + q * 4] = *(uint2*)h;
}

__global__ void k_pack2() {
    int i = blockIdx.x * blockDim.x + threadIdx.x;   // one per 4 elems, N*16 total
    if (i >= NN * 16) return;
    int r = i >> 4, q = i & 15;
    float4 v = *(const float4*)&g_C2[r * 128 + q * 4];
    __half h[4] = { __float2half(v.x), __float2half(v.y), __float2half(v.z), __float2half(v.w) };
    *(uint2*)&g_x2h[r * 64 + q * 4] = *(uint2*)h;
}

// ---------------- WMMA bf16 GEMM (preconverted operands) ----------------
#define GBM 128
#define GBN 128
#define GBK 32
#define GLDA 40
#define SM_A_BYTES (GBM * GLDA * 2)                 // 10240
#define SM_GEMM_TOTAL (4 * SM_A_BYTES + 16 * GBN * 4)   // 49152

template <int LAYER>
__global__ void __launch_bounds__(256)
k_gemm_mma(const float* __restrict__ bias0, const float* __restrict__ bias1)
{
    extern __shared__ char smem[];
    __nv_bfloat16* As_h = (__nv_bfloat16*)(smem);
    __nv_bfloat16* As_l = (__nv_bfloat16*)(smem + SM_A_BYTES);
    __nv_bfloat16* Bs_h = (__nv_bfloat16*)(smem + 2 * SM_A_BYTES);
    __nv_bfloat16* Bs_l = (__nv_bfloat16*)(smem + 3 * SM_A_BYTES);
    float* BiasT = (float*)(smem + 4 * SM_A_BYTES);

    float* C        = (LAYER == 1) ? g_C1 : g_C2;
    const __nv_bfloat16* Wh = (LAYER == 1) ? g_Bh : g_Bh2;
    const __nv_bfloat16* Wl = (LAYER == 1) ? g_Bl : g_Bl2;
    const int split = (LAYER == 1) ? 128 : 64;
    const int NB    = 2 * split;

    int tid = threadIdx.x;
    int wid = tid >> 5;
    int lane = tid & 31;
    int rowBase = blockIdx.x * GBM;
    int colBase = blockIdx.y * GBN;
    int wm = (wid & 3) * 32;
    int wn = (wid >> 2) * 64;

    #pragma unroll
    for (int it = 0; it < 8; it++) {
        int idx = tid + it * 256;
        int c = idx & 127, r = idx >> 7;
        int col = colBase + c;
        float bv = (col < split) ? bias0[col] : bias1[col - split];
        BiasT[r * 128 + c] = bv;
    }
    __syncthreads();

    wmma::fragment<wmma::accumulator, 16, 16, 16, float> acc[2][4];
    #pragma unroll
    for (int m = 0; m < 2; m++)
        #pragma unroll
        for (int n = 0; n < 4; n++)
            wmma::load_matrix_sync(acc[m][n], &BiasT[wn + 16 * n], 128, wmma::mem_row_major);

    #pragma unroll
    for (int stage = 0; stage < 4; stage++) {
        int kb = stage * GBK;
        if (stage) __syncthreads();

        #pragma unroll
        for (int it = 0; it < 2; it++) {
            int idx = tid + it * 256;
            int kq = idx & 3, r = idx >> 2;
            int gr = rowBase + r;
            uint4 vh = make_uint4(0, 0, 0, 0), vl = make_uint4(0, 0, 0, 0);
            if (gr < NN) {
                vh = *(const uint4*)&g_Ah[gr * 128 + kb + kq * 8];
                vl = *(const uint4*)&g_Al[gr * 128 + kb + kq * 8];
            }
            *(uint4*)&As_h[r * GLDA + kq * 8] = vh;
            *(uint4*)&As_l[r * GLDA + kq * 8] = vl;
        }
        #pragma unroll
        for (int it = 0; it < 2; it++) {
            int idx = tid + it * 256;
            int kq = idx & 3, n = idx >> 2;
            int gn = colBase + n;
            uint4 vh = *(const uint4*)&Wh[gn * 128 + kb + kq * 8];
            uint4 vl = *(const uint4*)&Wl[gn * 128 + kb + kq * 8];
            *(uint4*)&Bs_h[n * GLDA + kq * 8] = vh;
            *(uint4*)&Bs_l[n * GLDA + kq * 8] = vl;
        }
        __syncthreads();

        #pragma unroll
        for (int ks = 0; ks < 2; ks++) {
            wmma::fragment<wmma::matrix_a, 16, 16, 16, __nv_bfloat16, wmma::row_major> ah[2], al[2];
            #pragma unroll
            for (int m = 0; m < 2; m++) {
                wmma::load_matrix_sync(ah[m], &As_h[(wm + 16 * m) * GLDA + ks * 16], GLDA);
                wmma::load_matrix_sync(al[m], &As_l[(wm + 16 * m) * GLDA + ks * 16], GLDA);
            }
            #pragma unroll
            for (int n = 0; n < 4; n++) {
                wmma::fragment<wmma::matrix_b, 16, 16, 16, __nv_bfloat16, wmma::col_major> bh, bl;
                wmma::load_matrix_sync(bh, &Bs_h[(wn + 16 * n) * GLDA + ks * 16], GLDA);
                wmma::load_matrix_sync(bl, &Bs_l[(wn + 16 * n) * GLDA + ks * 16], GLDA);
                #pragma unroll
                for (int m = 0; m < 2; m++) {
                    wmma::mma_sync(acc[m][n], ah[m], bh, acc[m][n]);
                    wmma::mma_sync(acc[m][n], ah[m], bl, acc[m][n]);
                    wmma::mma_sync(acc[m][n], al[m], bh, acc[m][n]);
                }
            }
        }
    }

    if (rowBase + GBM <= NN) {
        #pragma unroll
        for (int m = 0; m < 2; m++)
            #pragma unroll
            for (int n = 0; n < 4; n++) {
                int gr = rowBase + wm + 16 * m;
                wmma::store_matrix_sync(&C[(size_t)gr * NB + colBase + wn + 16 * n],
                                        acc[m][n], NB, wmma::mem_row_major);
            }
    } else {
        __syncthreads();
        float* scr = (float*)smem + wid * 16 * 20;
        #pragma unroll
        for (int m = 0; m < 2; m++)
            #pragma unroll
            for (int n = 0; n < 4; n++) {
                wmma::store_matrix_sync(scr, acc[m][n], 20, wmma::mem_row_major);
                __syncwarp();
                int r = lane >> 1, c0 = (lane & 1) * 8;
                int gr = rowBase + wm + 16 * m + r;
                if (gr < NN) {
                    int gc = colBase + wn + 16 * n + c0;
                    #pragma unroll
                    for (int j = 0; j < 8; j++)
                        C[(size_t)gr * NB + gc + j] = scr[r * 20 + c0 + j];
                }
                __syncwarp();
            }
    }
}

// ---------------- layer-1 edge pass (fp16 gather, max-free softmax, unroll x8) ----------------
__global__ void __launch_bounds__(256)
k_edge1(const float* __restrict__ att1, const float* __restrict__ bias1)
{
    int warp = (blockIdx.x * blockDim.x + threadIdx.x) >> 5;
    int lane = threadIdx.x & 31;
    if (warp >= NN) return;
    int node = warp;
    int sub = lane & 3;
    int head = lane >> 2;

    float4 av = *(const float4*)&att1[head * 16 + sub * 4];
    float4 xr = *(const float4*)&g_C1[node * 256 + 128 + lane * 4];

    float s = 0.f;
    float4 acc = make_float4(0.f, 0.f, 0.f, 0.f);

    int beg = g_off[node], end = g_off[node + 1];
    int i = beg;

    #define E1_BODY(xv) do {                                                     \
        float2 fa = __half22float2(*(const __half2*)&(xv).x);                    \
        float2 fb = __half22float2(*(const __half2*)&(xv).y);                    \
        float t0 = fa.x + xr.x, t1 = fa.y + xr.y, t2 = fb.x + xr.z, t3 = fb.y + xr.w; \
        t0 = t0 > 0.f ? t0 : 0.2f * t0;  t1 = t1 > 0.f ? t1 : 0.2f * t1;         \
        t2 = t2 > 0.f ? t2 : 0.2f * t2;  t3 = t3 > 0.f ? t3 : 0.2f * t3;         \
        float p = t0 * av.x + t1 * av.y + t2 * av.z + t3 * av.w;                 \
        p += __shfl_xor_sync(0xffffffffu, p, 1);                                 \
        p += __shfl_xor_sync(0xffffffffu, p, 2);                                 \
        float e = __expf(p);                                                     \
        s += e;                                                                  \
        acc.x += e * fa.x; acc.y += e * fa.y; acc.z += e * fb.x; acc.w += e * fb.y; \
    } while (0)

    for (; i + 8 <= end; i += 8) {
        uint2 xv[8];
        #pragma unroll
        for (int u = 0; u < 8; u++)
            xv[u] = *(const uint2*)&g_x1h[g_csr[i + u] * 128 + lane * 4];
        #pragma unroll
        for (int u = 0; u < 8; u++) E1_BODY(xv[u]);
    }
    for (; i < end; i++) {
        uint2 xv = *(const uint2*)&g_x1h[g_csr[i] * 128 + lane * 4];
        E1_BODY(xv);
    }
    #undef E1_BODY

    float inv = 1.f / s;
    float4 bv = *(const float4*)&bias1[lane * 4];
    float o0 = acc.x * inv + bv.x;
    float o1 = acc.y * inv + bv.y;
    float o2 = acc.z * inv + bv.z;
    float o3 = acc.w * inv + bv.w;
    o0 = o0 > 0.f ? o0 : expm1f(o0);
    o1 = o1 > 0.f ? o1 : expm1f(o1);
    o2 = o2 > 0.f ? o2 : expm1f(o2);
    o3 = o3 > 0.f ? o3 : expm1f(o3);
    *(float4*)&g_h[node * 128 + lane * 4] = make_float4(o0, o1, o2, o3);

    // fused bf16 hi/lo conversion for layer-2 GEMM
    __nv_bfloat16 h[4], l[4];
    bf16_split(o0, h[0], l[0]);
    bf16_split(o1, h[1], l[1]);
    bf16_split(o2, h[2], l[2]);
    bf16_split(o3, h[3], l[3]);
    *(uint2*)&g_Ah[node * 128 + lane * 4] = *(uint2*)h;
    *(uint2*)&g_Al[node * 128 + lane * 4] = *(uint2*)l;
}

// ---------------- layer-2 edge pass (fp16 gather, 2 nodes/warp, unroll x8) ----------------
__global__ void __launch_bounds__(256)
k_edge2(const float* __restrict__ att2, const float* __restrict__ bias2,
        float* __restrict__ out)
{
    int warp = (blockIdx.x * blockDim.x + threadIdx.x) >> 5;
    int lane = threadIdx.x & 31;
    int node = warp * 2 + (lane >> 4);
    int l = lane & 15;
    if (node >= NN) return;
    unsigned hm = 0xFFFFu << (lane & 16);   // half-warp shuffle mask

    float4 av = *(const float4*)&att2[l * 4];
    float4 xr = *(const float4*)&g_C2[node * 128 + 64 + l * 4];

    float s = 0.f;
    float4 acc = make_float4(0.f, 0.f, 0.f, 0.f);

    int beg = g_off[node], end = g_off[node + 1];
    int i = beg;

    #define E2_BODY(xv) do {                                                     \
        float2 fa = __half22float2(*(const __half2*)&(xv).x);                    \
        float2 fb = __half22float2(*(const __half2*)&(xv).y);                    \
        float t0 = fa.x + xr.x, t1 = fa.y + xr.y, t2 = fb.x + xr.z, t3 = fb.y + xr.w; \
        t0 = t0 > 0.f ? t0 : 0.2f * t0;  t1 = t1 > 0.f ? t1 : 0.2f * t1;         \
        t2 = t2 > 0.f ? t2 : 0.2f * t2;  t3 = t3 > 0.f ? t3 : 0.2f * t3;         \
        float p = t0 * av.x + t1 * av.y + t2 * av.z + t3 * av.w;                 \
        p += __shfl_xor_sync(hm, p, 1);                                          \
        p += __shfl_xor_sync(hm, p, 2);                                          \
        p += __shfl_xor_sync(hm, p, 4);                                          \
        p += __shfl_xor_sync(hm, p, 8);                                          \
        float e = __expf(p);                                                     \
        s += e;                                                                  \
        acc.x += e * fa.x; acc.y += e * fa.y; acc.z += e * fb.x; acc.w += e * fb.y; \
    } while (0)

    for (; i + 8 <= end; i += 8) {
        uint2 xv[8];
        #pragma unroll
        for (int u = 0; u < 8; u++)
            xv[u] = *(const uint2*)&g_x2h[g_csr[i + u] * 64 + l * 4];
        #pragma unroll
        for (int u = 0; u < 8; u++) E2_BODY(xv[u]);
    }
    for (; i < end; i++) {
        uint2 xv = *(const uint2*)&g_x2h[g_csr[i] * 64 + l * 4];
        E2_BODY(xv);
    }
    #undef E2_BODY

    float inv = 1.f / s;
    float4 bv = *(const float4*)&bias2[l * 4];
    float4 o;
    o.x = acc.x * inv + bv.x;
    o.y = acc.y * inv + bv.y;
    o.z = acc.z * inv + bv.z;
    o.w = acc.w * inv + bv.w;
    *(float4*)&out[node * 64 + l * 4] = o;
}

// ---------------- launch ----------------
extern "C" void kernel_launch(void* const* d_in, const int* in_sizes, int n_in,
                              void* d_out, int out_size)
{
    const float* x     = (const float*)d_in[0];
    const void*  ei    = d_in[1];
    const float* W1l   = (const float*)d_in[2];
    const float* b1l   = (const float*)d_in[3];
    const float* W1r   = (const float*)d_in[4];
    const float* b1r   = (const float*)d_in[5];
    const float* att1  = (const float*)d_in[6];
    const float* bias1 = (const float*)d_in[7];
    const float* W2l   = (const float*)d_in[8];
    const float* b2l   = (const float*)d_in[9];
    const float* W2r   = (const float*)d_in[10];
    const float* b2r   = (const float*)d_in[11];
    const float* att2  = (const float*)d_in[12];
    const float* bias2 = (const float*)d_in[13];
    float* out = (float*)d_out;

    // Lazy one-time creation (first call is the non-captured correctness run)
    static cudaStream_t s2 = nullptr;
    static cudaEvent_t evA = nullptr, evB = nullptr;
    static bool tried = false;
    if (!tried) {
        tried = true;
        if (cudaStreamCreateWithFlags(&s2, cudaStreamNonBlocking) != cudaSuccess) { s2 = nullptr; }
        if (s2) {
            if (cudaEventCreateWithFlags(&evA, cudaEventDisableTiming) != cudaSuccess ||
                cudaEventCreateWithFlags(&evB, cudaEventDisableTiming) != cudaSuccess) {
                s2 = nullptr;
            }
        }
    }
    cudaStream_t cs = s2 ? s2 : (cudaStream_t)0;

    // Fork: CSR build on cs, concurrent with conv+GEMM1 on stream 0
    if (s2) { cudaEventRecord(evA, 0); cudaStreamWaitEvent(s2, evA, 0); }

    k_init   <<<(NN + 255) / 256, 256, 0, cs>>>(ei);
    k_hist   <<<(EE + 255) / 256, 256, 0, cs>>>(ei);
    int nsb = (NN + 1023) / 1024;           // 49
    k_scan1  <<<nsb, 1024, 0, cs>>>();
    k_scan3  <<<nsb, 1024, 0, cs>>>();
    k_scatter<<<(TOT_E + 255) / 256, 256, 0, cs>>>(ei);

    // Main chain on stream 0
    k_convA1 <<<(NN * 32 + 255) / 256, 256>>>(x);
    k_convW<1><<<(256 * 128 + 255) / 256, 256>>>(W1l, W1r);
    k_convW<2><<<(128 * 128 + 255) / 256, 256>>>(W2l, W2r);
    {
        dim3 grid((NN + 127) / 128, 2);
        k_gemm_mma<1><<<grid, 256, SM_GEMM_TOTAL>>>(b1l, b1r);
    }
    k_pack1<<<(NN * 32 + 255) / 256, 256>>>();

    // Join: edge1 needs CSR
    if (s2) { cudaEventRecord(evB, s2); cudaStreamWaitEvent(0, evB, 0); }

    k_edge1<<<(NN * 32 + 255) / 256, 256>>>(att1, bias1);  // writes g_h + bf16 split

    {
        dim3 grid((NN + 127) / 128, 1);
        k_gemm_mma<2><<<grid, 256, SM_GEMM_TOTAL>>>(b2l, b2r);
    }
    k_pack2<<<(NN * 16 + 255) / 256, 256>>>();
    k_edge2<<<(NN * 16 + 255) / 256, 256>>>(att2, bias2, out);

    (void)in_sizes; (void)n_in; (void)out_size;
}

// round 15
// speedup vs baseline: 1.0440x; 1.0440x over previous
#include <cuda_runtime.h>
#include <cuda_bf16.h>
#include <mma.h>
#include <cstdint>

using namespace nvcuda;

// Problem constants (fixed by the dataset)
#define NN 50000
#define EE 800000
#define TOT_E (EE + NN)   // edges + self loops = 850000

// ---------------- scratch (no allocations allowed) ----------------
__device__ __align__(16) float g_C1[NN * 256];   // [xl1 | xr1] per node (128+128)
__device__ __align__(16) float g_h [NN * 128];   // layer-1 output after ELU
__device__ __align__(16) float g_C2[NN * 128];   // [xl2 | xr2] per node (64+64)
__device__ __align__(16) __nv_bfloat16 g_Ah[NN * 128];   // A hi (bf16 split)
__device__ __align__(16) __nv_bfloat16 g_Al[NN * 128];   // A lo
__device__ __align__(16) __nv_bfloat16 g_Bh[256 * 128];  // layer-1 W transposed [n][k] hi
__device__ __align__(16) __nv_bfloat16 g_Bl[256 * 128];  // layer-1 W transposed [n][k] lo
__device__ __align__(16) __nv_bfloat16 g_Bh2[128 * 128]; // layer-2 W transposed hi
__device__ __align__(16) __nv_bfloat16 g_Bl2[128 * 128]; // layer-2 W transposed lo
__device__ int   g_deg[NN];
__device__ int   g_tmp[NN];
__device__ int   g_off[NN + 1];
__device__ int   g_cur[NN];
__device__ int   g_bsum[64];
__device__ int   g_csr[TOT_E];
__device__ int   g_is64;          // 1 if edge_index is int64, 0 if int32

// ---------------- edge-index dtype handling ----------------
__device__ __forceinline__ int edge_at(const void* ei, int idx) {
    if (g_is64) return (int)((const long long*)ei)[idx];
    return ((const int*)ei)[idx];
}

// ---------------- CSR build ----------------
__global__ void k_init(const void* __restrict__ ei) {
    int i = blockIdx.x * blockDim.x + threadIdx.x;
    if (i < NN) g_deg[i] = 1;   // self loop
    if (i == 0) {
        const long long* p = (const long long*)ei;
        int ok = 1;
        for (int j = 0; j < 64; j++) {
            long long v = p[j];
            if (v < 0 || v >= NN) { ok = 0; break; }
        }
        g_is64 = ok;
    }
}

__global__ void k_hist(const void* __restrict__ ei) {
    int e = blockIdx.x * blockDim.x + threadIdx.x;
    if (e < EE) {
        int d = edge_at(ei, EE + e);
        atomicAdd(&g_deg[d], 1);
    }
}

__global__ void k_scan1() {
    __shared__ int sh[1024];
    int t = threadIdx.x;
    int i = blockIdx.x * 1024 + t;
    int v = (i < NN) ? g_deg[i] : 0;
    sh[t] = v;
    __syncthreads();
    #pragma unroll
    for (int off = 1; off < 1024; off <<= 1) {
        int x = (t >= off) ? sh[t - off] : 0;
        __syncthreads();
        sh[t] += x;
        __syncthreads();
    }
    if (i < NN) g_tmp[i] = sh[t] - v;
    if (t == 1023) g_bsum[blockIdx.x] = sh[1023];
}

// scan3 with scan2 folded in (block leader sums prior block totals)
__global__ void k_scan3() {
    __shared__ int base;
    if (threadIdx.x == 0) {
        int run = 0;
        for (int b = 0; b < (int)blockIdx.x; b++) run += g_bsum[b];
        base = run;
    }
    __syncthreads();
    int i = blockIdx.x * 1024 + threadIdx.x;
    if (i < NN) {
        int off = g_tmp[i] + base;
        g_off[i] = off;
        g_cur[i] = off;
        if (i == NN - 1) g_off[NN] = off + g_deg[i];
    }
}

__global__ void k_scatter(const void* __restrict__ ei) {
    int id = blockIdx.x * blockDim.x + threadIdx.x;
    if (id >= TOT_E) return;
    int s, d;
    if (id < EE) { s = edge_at(ei, id); d = edge_at(ei, EE + id); }
    else         { s = d = id - EE; }
    int p = atomicAdd(&g_cur[d], 1);
    g_csr[p] = s;
}

// ---------------- bf16 hi/lo split helpers ----------------
__device__ __forceinline__ void bf16_split(float v, __nv_bfloat16& h, __nv_bfloat16& l) {
    h = __float2bfloat16(v);
    l = __float2bfloat16(v - __bfloat162float(h));
}

// ---------------- fused conversion kernel: A1 + W1 + W2 ----------------
// block range [0, AB)          : A (NN*32 float4 items)
// block range [AB, AB+W1B)     : W1 (256*128 scalar items)
// block range [AB+W1B, +W2B)   : W2 (128*128 scalar items)
#define AB  ((NN * 32 + 255) / 256)          // 6250
#define W1B ((256 * 128 + 255) / 256)        // 128
#define W2B ((128 * 128 + 255) / 256)        // 64

__global__ void k_convAll(const float* __restrict__ A,
                          const float* __restrict__ W1l, const float* __restrict__ W1r,
                          const float* __restrict__ W2l, const float* __restrict__ W2r)
{
    int b = blockIdx.x;
    if (b < AB) {
        int i = b * 256 + threadIdx.x;
        if (i >= NN * 32) return;
        float4 v = *(const float4*)&A[i * 4];
        __nv_bfloat16 h[4], l[4];
        bf16_split(v.x, h[0], l[0]);
        bf16_split(v.y, h[1], l[1]);
        bf16_split(v.z, h[2], l[2]);
        bf16_split(v.w, h[3], l[3]);
        *(uint2*)&g_Ah[i * 4] = *(uint2*)h;
        *(uint2*)&g_Al[i * 4] = *(uint2*)l;
    } else if (b < AB + W1B) {
        int idx = (b - AB) * 256 + threadIdx.x;
        if (idx >= 256 * 128) return;
        int n = idx % 256, k = idx / 256;
        const float* W = (n < 128) ? W1l : W1r;
        int wc = (n < 128) ? n : n - 128;
        float v = W[k * 128 + wc];
        __nv_bfloat16 h, l;
        bf16_split(v, h, l);
        g_Bh[n * 128 + k] = h;
        g_Bl[n * 128 + k] = l;
    } else {
        int idx = (b - AB - W1B) * 256 + threadIdx.x;
        if (idx >= 128 * 128) return;
        int n = idx % 128, k = idx / 128;
        const float* W = (n < 64) ? W2l : W2r;
        int wc = (n < 64) ? n : n - 64;
        float v = W[k * 64 + wc];
        __nv_bfloat16 h, l;
        bf16_split(v, h, l);
        g_Bh2[n * 128 + k] = h;
        g_Bl2[n * 128 + k] = l;
    }
}

// ---------------- WMMA bf16 GEMM (preconverted operands) ----------------
#define GBM 128
#define GBN 128
#define GBK 32
#define GLDA 40
#define SM_A_BYTES (GBM * GLDA * 2)                 // 10240
#define SM_GEMM_TOTAL (4 * SM_A_BYTES + 16 * GBN * 4)   // 49152

template <int LAYER>
__global__ void __launch_bounds__(256)
k_gemm_mma(const float* __restrict__ bias0, const float* __restrict__ bias1)
{
    extern __shared__ char smem[];
    __nv_bfloat16* As_h = (__nv_bfloat16*)(smem);
    __nv_bfloat16* As_l = (__nv_bfloat16*)(smem + SM_A_BYTES);
    __nv_bfloat16* Bs_h = (__nv_bfloat16*)(smem + 2 * SM_A_BYTES);
    __nv_bfloat16* Bs_l = (__nv_bfloat16*)(smem + 3 * SM_A_BYTES);
    float* BiasT = (float*)(smem + 4 * SM_A_BYTES);

    float* C        = (LAYER == 1) ? g_C1 : g_C2;
    const __nv_bfloat16* Wh = (LAYER == 1) ? g_Bh : g_Bh2;
    const __nv_bfloat16* Wl = (LAYER == 1) ? g_Bl : g_Bl2;
    const int split = (LAYER == 1) ? 128 : 64;
    const int NB    = 2 * split;

    int tid = threadIdx.x;
    int wid = tid >> 5;
    int lane = tid & 31;
    int rowBase = blockIdx.x * GBM;
    int colBase = blockIdx.y * GBN;
    int wm = (wid & 3) * 32;
    int wn = (wid >> 2) * 64;

    #pragma unroll
    for (int it = 0; it < 8; it++) {
        int idx = tid + it * 256;
        int c = idx & 127, r = idx >> 7;
        int col = colBase + c;
        float bv = (col < split) ? bias0[col] : bias1[col - split];
        BiasT[r * 128 + c] = bv;
    }
    __syncthreads();

    wmma::fragment<wmma::accumulator, 16, 16, 16, float> acc[2][4];
    #pragma unroll
    for (int m = 0; m < 2; m++)
        #pragma unroll
        for (int n = 0; n < 4; n++)
            wmma::load_matrix_sync(acc[m][n], &BiasT[wn + 16 * n], 128, wmma::mem_row_major);

    #pragma unroll
    for (int stage = 0; stage < 4; stage++) {
        int kb = stage * GBK;
        if (stage) __syncthreads();

        #pragma unroll
        for (int it = 0; it < 2; it++) {
            int idx = tid + it * 256;
            int kq = idx & 3, r = idx >> 2;
            int gr = rowBase + r;
            uint4 vh = make_uint4(0, 0, 0, 0), vl = make_uint4(0, 0, 0, 0);
            if (gr < NN) {
                vh = *(const uint4*)&g_Ah[gr * 128 + kb + kq * 8];
                vl = *(const uint4*)&g_Al[gr * 128 + kb + kq * 8];
            }
            *(uint4*)&As_h[r * GLDA + kq * 8] = vh;
            *(uint4*)&As_l[r * GLDA + kq * 8] = vl;
        }
        #pragma unroll
        for (int it = 0; it < 2; it++) {
            int idx = tid + it * 256;
            int kq = idx & 3, n = idx >> 2;
            int gn = colBase + n;
            uint4 vh = *(const uint4*)&Wh[gn * 128 + kb + kq * 8];
            uint4 vl = *(const uint4*)&Wl[gn * 128 + kb + kq * 8];
            *(uint4*)&Bs_h[n * GLDA + kq * 8] = vh;
            *(uint4*)&Bs_l[n * GLDA + kq * 8] = vl;
        }
        __syncthreads();

        #pragma unroll
        for (int ks = 0; ks < 2; ks++) {
            wmma::fragment<wmma::matrix_a, 16, 16, 16, __nv_bfloat16, wmma::row_major> ah[2], al[2];
            #pragma unroll
            for (int m = 0; m < 2; m++) {
                wmma::load_matrix_sync(ah[m], &As_h[(wm + 16 * m) * GLDA + ks * 16], GLDA);
                wmma::load_matrix_sync(al[m], &As_l[(wm + 16 * m) * GLDA + ks * 16], GLDA);
            }
            #pragma unroll
            for (int n = 0; n < 4; n++) {
                wmma::fragment<wmma::matrix_b, 16, 16, 16, __nv_bfloat16, wmma::col_major> bh, bl;
                wmma::load_matrix_sync(bh, &Bs_h[(wn + 16 * n) * GLDA + ks * 16], GLDA);
                wmma::load_matrix_sync(bl, &Bs_l[(wn + 16 * n) * GLDA + ks * 16], GLDA);
                #pragma unroll
                for (int m = 0; m < 2; m++) {
                    wmma::mma_sync(acc[m][n], ah[m], bh, acc[m][n]);
                    wmma::mma_sync(acc[m][n], ah[m], bl, acc[m][n]);
                    wmma::mma_sync(acc[m][n], al[m], bh, acc[m][n]);
                }
            }
        }
    }

    if (rowBase + GBM <= NN) {
        #pragma unroll
        for (int m = 0; m < 2; m++)
            #pragma unroll
            for (int n = 0; n < 4; n++) {
                int gr = rowBase + wm + 16 * m;
                wmma::store_matrix_sync(&C[(size_t)gr * NB + colBase + wn + 16 * n],
                                        acc[m][n], NB, wmma::mem_row_major);
            }
    } else {
        __syncthreads();
        float* scr = (float*)smem + wid * 16 * 20;
        #pragma unroll
        for (int m = 0; m < 2; m++)
            #pragma unroll
            for (int n = 0; n < 4; n++) {
                wmma::store_matrix_sync(scr, acc[m][n], 20, wmma::mem_row_major);
                __syncwarp();
                int r = lane >> 1, c0 = (lane & 1) * 8;
                int gr = rowBase + wm + 16 * m + r;
                if (gr < NN) {
                    int gc = colBase + wn + 16 * n + c0;
                    #pragma unroll
                    for (int j = 0; j < 8; j++)
                        C[(size_t)gr * NB + gc + j] = scr[r * 20 + c0 + j];
                }
                __syncwarp();
            }
    }
}

// ---------------- layer-1 edge pass (fp32 gather, max-free softmax, unroll x8) ----------------
__global__ void __launch_bounds__(256)
k_edge1(const float* __restrict__ att1, const float* __restrict__ bias1)
{
    int warp = (blockIdx.x * blockDim.x + threadIdx.x) >> 5;
    int lane = threadIdx.x & 31;
    if (warp >= NN) return;
    int node = warp;
    int sub = lane & 3;
    int head = lane >> 2;

    float4 av = *(const float4*)&att1[head * 16 + sub * 4];
    float4 xr = *(const float4*)&g_C1[node * 256 + 128 + lane * 4];

    float s = 0.f;
    float4 acc = make_float4(0.f, 0.f, 0.f, 0.f);

    int beg = g_off[node], end = g_off[node + 1];
    int i = beg;

    #define E1_BODY(xl) do {                                                     \
        float t0 = xl.x + xr.x, t1 = xl.y + xr.y, t2 = xl.z + xr.z, t3 = xl.w + xr.w; \
        t0 = t0 > 0.f ? t0 : 0.2f * t0;  t1 = t1 > 0.f ? t1 : 0.2f * t1;         \
        t2 = t2 > 0.f ? t2 : 0.2f * t2;  t3 = t3 > 0.f ? t3 : 0.2f * t3;         \
        float p = t0 * av.x + t1 * av.y + t2 * av.z + t3 * av.w;                 \
        p += __shfl_xor_sync(0xffffffffu, p, 1);                                 \
        p += __shfl_xor_sync(0xffffffffu, p, 2);                                 \
        float e = __expf(p);                                                     \
        s += e;                                                                  \
        acc.x += e * xl.x; acc.y += e * xl.y; acc.z += e * xl.z; acc.w += e * xl.w; \
    } while (0)

    for (; i + 8 <= end; i += 8) {
        float4 xv[8];
        #pragma unroll
        for (int u = 0; u < 8; u++)
            xv[u] = *(const float4*)&g_C1[g_csr[i + u] * 256 + lane * 4];
        #pragma unroll
        for (int u = 0; u < 8; u++) E1_BODY(xv[u]);
    }
    for (; i < end; i++) {
        float4 xv = *(const float4*)&g_C1[g_csr[i] * 256 + lane * 4];
        E1_BODY(xv);
    }
    #undef E1_BODY

    float inv = 1.f / s;
    float4 bv = *(const float4*)&bias1[lane * 4];
    float o0 = acc.x * inv + bv.x;
    float o1 = acc.y * inv + bv.y;
    float o2 = acc.z * inv + bv.z;
    float o3 = acc.w * inv + bv.w;
    o0 = o0 > 0.f ? o0 : expm1f(o0);
    o1 = o1 > 0.f ? o1 : expm1f(o1);
    o2 = o2 > 0.f ? o2 : expm1f(o2);
    o3 = o3 > 0.f ? o3 : expm1f(o3);
    *(float4*)&g_h[node * 128 + lane * 4] = make_float4(o0, o1, o2, o3);

    // fused bf16 hi/lo conversion for layer-2 GEMM
    __nv_bfloat16 h[4], l[4];
    bf16_split(o0, h[0], l[0]);
    bf16_split(o1, h[1], l[1]);
    bf16_split(o2, h[2], l[2]);
    bf16_split(o3, h[3], l[3]);
    *(uint2*)&g_Ah[node * 128 + lane * 4] = *(uint2*)h;
    *(uint2*)&g_Al[node * 128 + lane * 4] = *(uint2*)l;
}

// ---------------- layer-2 edge pass (fp32 gather, 2 nodes/warp, unroll x8) ----------------
__global__ void __launch_bounds__(256)
k_edge2(const float* __restrict__ att2, const float* __restrict__ bias2,
        float* __restrict__ out)
{
    int warp = (blockIdx.x * blockDim.x + threadIdx.x) >> 5;
    int lane = threadIdx.x & 31;
    int node = warp * 2 + (lane >> 4);
    int l = lane & 15;
    if (node >= NN) return;
    unsigned hm = 0xFFFFu << (lane & 16);   // half-warp shuffle mask

    float4 av = *(const float4*)&att2[l * 4];
    float4 xr = *(const float4*)&g_C2[node * 128 + 64 + l * 4];

    float s = 0.f;
    float4 acc = make_float4(0.f, 0.f, 0.f, 0.f);

    int beg = g_off[node], end = g_off[node + 1];
    int i = beg;

    #define E2_BODY(xl) do {                                                     \
        float t0 = xl.x + xr.x, t1 = xl.y + xr.y, t2 = xl.z + xr.z, t3 = xl.w + xr.w; \
        t0 = t0 > 0.f ? t0 : 0.2f * t0;  t1 = t1 > 0.f ? t1 : 0.2f * t1;         \
        t2 = t2 > 0.f ? t2 : 0.2f * t2;  t3 = t3 > 0.f ? t3 : 0.2f * t3;         \
        float p = t0 * av.x + t1 * av.y + t2 * av.z + t3 * av.w;                 \
        p += __shfl_xor_sync(hm, p, 1);                                          \
        p += __shfl_xor_sync(hm, p, 2);                                          \
        p += __shfl_xor_sync(hm, p, 4);                                          \
        p += __shfl_xor_sync(hm, p, 8);                                          \
        float e = __expf(p);                                                     \
        s += e;                                                                  \
        acc.x += e * xl.x; acc.y += e * xl.y; acc.z += e * xl.z; acc.w += e * xl.w; \
    } while (0)

    for (; i + 8 <= end; i += 8) {
        float4 xv[8];
        #pragma unroll
        for (int u = 0; u < 8; u++)
            xv[u] = *(const float4*)&g_C2[g_csr[i + u] * 128 + l * 4];
        #pragma unroll
        for (int u = 0; u < 8; u++) E2_BODY(xv[u]);
    }
    for (; i < end; i++) {
        float4 xv = *(const float4*)&g_C2[g_csr[i] * 128 + l * 4];
        E2_BODY(xv);
    }
    #undef E2_BODY

    float inv = 1.f / s;
    float4 bv = *(const float4*)&bias2[l * 4];
    float4 o;
    o.x = acc.x * inv + bv.x;
    o.y = acc.y * inv + bv.y;
    o.z = acc.z * inv + bv.z;
    o.w = acc.w * inv + bv.w;
    *(float4*)&out[node * 64 + l * 4] = o;
}

// ---------------- launch ----------------
extern "C" void kernel_launch(void* const* d_in, const int* in_sizes, int n_in,
                              void* d_out, int out_size)
{
    const float* x     = (const float*)d_in[0];
    const void*  ei    = d_in[1];
    const float* W1l   = (const float*)d_in[2];
    const float* b1l   = (const float*)d_in[3];
    const float* W1r   = (const float*)d_in[4];
    const float* b1r   = (const float*)d_in[5];
    const float* att1  = (const float*)d_in[6];
    const float* bias1 = (const float*)d_in[7];
    const float* W2l   = (const float*)d_in[8];
    const float* b2l   = (const float*)d_in[9];
    const float* W2r   = (const float*)d_in[10];
    const float* b2r   = (const float*)d_in[11];
    const float* att2  = (const float*)d_in[12];
    const float* bias2 = (const float*)d_in[13];
    float* out = (float*)d_out;

    // Lazy one-time creation (first call is the non-captured correctness run)
    static cudaStream_t s2 = nullptr;
    static cudaEvent_t evA = nullptr, evB = nullptr;
    static bool tried = false;
    if (!tried) {
        tried = true;
        if (cudaStreamCreateWithFlags(&s2, cudaStreamNonBlocking) != cudaSuccess) { s2 = nullptr; }
        if (s2) {
            if (cudaEventCreateWithFlags(&evA, cudaEventDisableTiming) != cudaSuccess ||
                cudaEventCreateWithFlags(&evB, cudaEventDisableTiming) != cudaSuccess) {
                s2 = nullptr;
            }
        }
    }
    cudaStream_t cs = s2 ? s2 : (cudaStream_t)0;

    // Fork: CSR build on cs, concurrent with conv+GEMM1 on stream 0
    if (s2) { cudaEventRecord(evA, 0); cudaStreamWaitEvent(s2, evA, 0); }

    k_init   <<<(NN + 255) / 256, 256, 0, cs>>>(ei);
    k_hist   <<<(EE + 255) / 256, 256, 0, cs>>>(ei);
    int nsb = (NN + 1023) / 1024;           // 49
    k_scan1  <<<nsb, 1024, 0, cs>>>();
    k_scan3  <<<nsb, 1024, 0, cs>>>();
    k_scatter<<<(TOT_E + 255) / 256, 256, 0, cs>>>(ei);

    // Main chain on stream 0
    k_convAll<<<AB + W1B + W2B, 256>>>(x, W1l, W1r, W2l, W2r);
    {
        dim3 grid((NN + 127) / 128, 2);
        k_gemm_mma<1><<<grid, 256, SM_GEMM_TOTAL>>>(b1l, b1r);
    }

    // Join: edge1 needs CSR
    if (s2) { cudaEventRecord(evB, s2); cudaStreamWaitEvent(0, evB, 0); }

    k_edge1<<<(NN * 32 + 255) / 256, 256>>>(att1, bias1);  // writes g_h + bf16 split

    {
        dim3 grid((NN + 127) / 128, 1);
        k_gemm_mma<2><<<grid, 256, SM_GEMM_TOTAL>>>(b2l, b2r);
    }
    k_edge2<<<(NN * 16 + 255) / 256, 256>>>(att2, bias2, out);

    (void)in_sizes; (void)n_in; (void)out_size;
}